// round 16
// baseline (speedup 1.0000x reference)
#include <cuda_runtime.h>
#include <math.h>

// Problem constants
#define NB   16
#define W    64
#define TD   8192
#define NT   (NB * TD)        // 131072 rows
#define KB   2048             // codebook size
#define TM   128              // t-rows per block
#define TN   128              // codes per tile
#define NKT  (KB / TN)        // 16 code tiles
#define NTHR 256

// smem layout (floats): xs[64][128] | ks0 | ks1 | scratch | idx | arow[128]
#define SM_XS    0
#define SM_KS0   8192
#define SM_KS1   16384
#define SM_SCR   24576
#define SM_IDX   24704
#define SM_AR    24832
#define SMEM_FLOATS 24960
#define SMEM_BYTES  (SMEM_FLOATS * 4)      // 99840 B; x2 CTA = 199680 < 228 KB

// __device__ scratch (allocation-free rule: globals only)
__device__ __align__(16) float g_kT[W * KB];   // transposed codebook [w][c]
__device__ float  g_knorm[KB];                 // ||k_c||^2 (reference rounding order)
__device__ double g_sum;
__device__ double g_sumsq;
__device__ double g_fit;

// Transpose codebook + per-code squared norms + zero accumulators (once per launch)
__global__ void vq_prep(const float* __restrict__ k) {
    int idx = blockIdx.x * blockDim.x + threadIdx.x;
    if (idx == 0) { g_sum = 0.0; g_sumsq = 0.0; g_fit = 0.0; }
    if (idx < W * KB) {
        int w = idx >> 11;          // / 2048
        int c = idx & (KB - 1);
        g_kT[idx] = k[c * W + w];
    }
    if (idx < KB) {
        const float* kr = k + idx * W;
        // replicate XLA reduce: sequential add of rounded squares (NOT fma)
        float s = 0.f;
        for (int w = 0; w < W; ++w) {
            float v = kr[w];
            s = __fadd_rn(s, __fmul_rn(v, v));
        }
        g_knorm[idx] = s;
    }
}

// packed fp32x2 FMA: d = a*b + d (exact fp32 per lane, 2x FFMA throughput)
__device__ __forceinline__ void ffma2(float2& d, const float2& a, const float2& b) {
    asm("fma.rn.f32x2 %0, %1, %2, %0;"
        : "+l"(reinterpret_cast<unsigned long long&>(d))
        : "l"(reinterpret_cast<const unsigned long long&>(a)),
          "l"(reinterpret_cast<const unsigned long long&>(b)));
}

// 16B async global->shared copy (bypasses registers)
__device__ __forceinline__ void cp_async16(float* smem_dst, const float* gsrc) {
    unsigned sa = (unsigned)__cvta_generic_to_shared(smem_dst);
    asm volatile("cp.async.cg.shared.global [%0], [%1], 16;" :: "r"(sa), "l"(gsrc));
}

__global__ void __launch_bounds__(NTHR, 2)
vq_main(const float* __restrict__ x, float* __restrict__ out)
{
    extern __shared__ float smem[];
    float* xs    = smem + SM_XS;            // [w][t]
    float* rscr  = smem + SM_SCR;
    int*   idx_s = (int*)(smem + SM_IDX);
    float* arow  = smem + SM_AR;            // per-row ||x||^2 (reference rounding)
    float* redv  = smem + SM_KS0;           // [row][16] alias (post-compute)
    int*   redi  = (int*)(smem + SM_KS0 + TM * 16);

    const int tid  = threadIdx.x;
    const int tx   = tid & 15;
    const int ty   = tid >> 4;
    const int row0 = ty * 8;
    const int b    = blockIdx.x;
    const int n    = b >> 6;                // 64 tiles per batch item
    const int t0   = (b & 63) * TM;

    const float* xb = x + ((size_t)n * W) * TD + t0;

    float* ks_cur = smem + SM_KS0;          // buffer holding the tile being computed
    float* ks_nxt = smem + SM_KS1;          // buffer being filled

    // ---- async prefetch: X tile + K tile 0 in one group ----
    #pragma unroll
    for (int e = 0; e < 8; ++e) {
        int idx = tid + e * NTHR;           // 0..2047 float4 units
        int w   = idx >> 5;
        int q4  = (idx & 31) << 2;
        cp_async16(xs + w * TM + q4, xb + (size_t)w * TD + q4);
        cp_async16(ks_cur + w * TM + q4, g_kT + w * KB + q4);
    }
    asm volatile("cp.async.commit_group;");
    asm volatile("cp.async.wait_group 0;");
    __syncthreads();                        // xs + K tile 0 resident

    // ---- prenorm partial sums from smem-resident X tile ----
    float lsum = 0.f, lsq = 0.f;
    #pragma unroll
    for (int e = 0; e < 8; ++e) {
        int idx = tid + e * NTHR;
        float4 v = *(const float4*)(xs + ((idx >> 5) * TM) + ((idx & 31) << 2));
        lsum += (v.x + v.y) + (v.z + v.w);
        lsq  = fmaf(v.x, v.x, lsq); lsq = fmaf(v.y, v.y, lsq);
        lsq  = fmaf(v.z, v.z, lsq); lsq = fmaf(v.w, v.w, lsq);
    }

    // ---- per-row A = sum(x^2) in reference order: sequential add of rounded squares ----
    if (tid < TM) {
        float a = 0.f;
        for (int w = 0; w < W; ++w) {
            float t = xs[w * TM + tid];
            a = __fadd_rn(a, __fmul_rn(t, t));
        }
        arow[tid] = a;
    }
    __syncthreads();

    float best[8];
    int   bidx[8];
    #pragma unroll
    for (int i = 0; i < 8; ++i) { best[i] = 3.0e38f; bidx[i] = 0; }

    for (int ct = 0; ct < NKT; ++ct) {
        const int c0 = ct * TN;

        // prefetch tile ct+1 into the other buffer (uniform branch)
        if (ct + 1 < NKT) {
            const float* src = g_kT + (c0 + TN);
            #pragma unroll
            for (int e = 0; e < 8; ++e) {
                int idx = tid + e * NTHR;
                int w   = idx >> 5;
                int c4  = (idx & 31) << 2;
                cp_async16(ks_nxt + w * TM + c4, src + w * KB + c4);
            }
            asm volatile("cp.async.commit_group;");
        }

        float2 acc[4][8];
        #pragma unroll
        for (int i = 0; i < 4; ++i)
            #pragma unroll
            for (int j = 0; j < 8; ++j) acc[i][j] = make_float2(0.f, 0.f);

        #pragma unroll 4
        for (int w = 0; w < W; ++w) {
            const float* xr = xs + w * TM + row0;
            float2 a0 = *(const float2*)(xr + 0);
            float2 a1 = *(const float2*)(xr + 2);
            float2 a2 = *(const float2*)(xr + 4);
            float2 a3 = *(const float2*)(xr + 6);
            const float* kr = ks_cur + w * TM + tx * 4;  // cols tx*4..+3 and +64
            float4 b0 = *(const float4*)(kr);
            float4 b1 = *(const float4*)(kr + 64);
            float2 bd[8];
            bd[0] = make_float2(b0.x, b0.x); bd[1] = make_float2(b0.y, b0.y);
            bd[2] = make_float2(b0.z, b0.z); bd[3] = make_float2(b0.w, b0.w);
            bd[4] = make_float2(b1.x, b1.x); bd[5] = make_float2(b1.y, b1.y);
            bd[6] = make_float2(b1.z, b1.z); bd[7] = make_float2(b1.w, b1.w);
            #pragma unroll
            for (int j = 0; j < 8; ++j) {
                ffma2(acc[0][j], a0, bd[j]);
                ffma2(acc[1][j], a1, bd[j]);
                ffma2(acc[2][j], a2, bd[j]);
                ffma2(acc[3][j], a3, bd[j]);
            }
        }

        // epilogue: dist = fl(fl(A - 2*dot) + knorm), running argmin (first-min)
        #pragma unroll
        for (int j = 0; j < 8; ++j) {
            int cl = (j < 4) ? (tx * 4 + j) : (64 + tx * 4 + (j - 4));
            int c  = c0 + cl;
            float knj = __ldg(g_knorm + c);
            #pragma unroll
            for (int i = 0; i < 4; ++i) {
                float A0 = arow[row0 + 2 * i];
                float A1 = arow[row0 + 2 * i + 1];
                float s0 = __fadd_rn(__fsub_rn(A0, 2.0f * acc[i][j].x), knj);
                float s1 = __fadd_rn(__fsub_rn(A1, 2.0f * acc[i][j].y), knj);
                if (s0 < best[2*i])   { best[2*i]   = s0; bidx[2*i]   = c; }
                if (s1 < best[2*i+1]) { best[2*i+1] = s1; bidx[2*i+1] = c; }
            }
        }

        // land tile ct+1; also orders next overwrite of ks_cur after these reads
        asm volatile("cp.async.wait_group 0;");   // no-op on final iteration
        __syncthreads();
        float* tmp = ks_cur; ks_cur = ks_nxt; ks_nxt = tmp;
    }

    // ---- cross-thread argmin reduce (16 threads share each row) ----
    #pragma unroll
    for (int i = 0; i < 8; ++i) {
        redv[(row0 + i) * 16 + tx] = best[i];
        redi[(row0 + i) * 16 + tx] = bidx[i];
    }
    __syncthreads();

    float myfit = 0.f;
    if (tid < TM) {
        int r = tid;
        float bv = redv[r * 16];
        int   bi = redi[r * 16];
        #pragma unroll
        for (int t = 1; t < 16; ++t) {
            float v  = redv[r * 16 + t];
            int   ci = redi[r * 16 + t];
            if (v < bv || (v == bv && ci < bi)) { bv = v; bi = ci; }
        }
        idx_s[r] = bi;
        myfit = bv;                          // quantized min distance (matches jnp.min)
        out[(size_t)n * TD + t0 + r] = (float)bi;   // x_l
    }
    __syncthreads();

    // ---- x_d: straight-through value fl(x + fl(k - x)), coalesced in t ----
    float* xd_out = out + NT + (size_t)n * W * TD + t0;
    #pragma unroll
    for (int e = 0; e < 32; ++e) {
        int idx  = tid + e * NTHR;           // 0..8191
        int w    = idx >> 7;
        int r    = idx & 127;
        int code = idx_s[r];
        float kv = __ldg(g_kT + w * KB + code);
        float xv = xs[w * TM + r];
        xd_out[(size_t)w * TD + r] = __fadd_rn(xv, __fsub_rn(kv, xv));
    }

    // ---- block reductions -> global accumulators ----
    #pragma unroll
    for (int o = 16; o > 0; o >>= 1) {
        lsum  += __shfl_down_sync(0xffffffffu, lsum,  o);
        lsq   += __shfl_down_sync(0xffffffffu, lsq,   o);
        myfit += __shfl_down_sync(0xffffffffu, myfit, o);
    }
    int lane = tid & 31, wrp = tid >> 5;
    if (lane == 0) { rscr[wrp] = lsum; rscr[8 + wrp] = lsq; rscr[16 + wrp] = myfit; }
    __syncthreads();
    if (tid == 0) {
        float bs = 0.f, bq = 0.f, bf = 0.f;
        #pragma unroll
        for (int i = 0; i < 8; ++i) { bs += rscr[i]; bq += rscr[8 + i]; bf += rscr[16 + i]; }
        atomicAdd(&g_sum,   (double)bs);
        atomicAdd(&g_sumsq, (double)bq);
        atomicAdd(&g_fit,   (double)bf);     // sum of quantized min distances
    }
}

__global__ void vq_final(float* __restrict__ out) {
    const double n_el = (double)NT * (double)W;   // 8388608
    double mean = g_sum / n_el;
    double var  = g_sumsq / n_el - mean * mean;
    if (var < 0.0) var = 0.0;
    const size_t base = (size_t)NT + (size_t)NT * W;   // after x_l and x_d
    out[base + 0] = (float)(g_fit / n_el);             // commit_loss = sum(min_d)/n_el
    out[base + 1] = (float)(g_fit / (double)NT);       // fit = mean(min_distance)
    out[base + 2] = (float)sqrt(var);                  // prenorm = ||x-mean||/sqrt(n)
}

extern "C" void kernel_launch(void* const* d_in, const int* in_sizes, int n_in,
                              void* d_out, int out_size) {
    const float* x = (const float*)d_in[0];   // (16, 64, 8192) fp32
    const float* k = (const float*)d_in[1];   // (2048, 64) fp32
    float* out = (float*)d_out;               // [x_l | x_d | commit, fit, prenorm]

    cudaFuncSetAttribute(vq_main, cudaFuncAttributeMaxDynamicSharedMemorySize, SMEM_BYTES);
    vq_prep<<<(W * KB + 255) / 256, 256>>>(k);
    vq_main<<<NT / TM, NTHR, SMEM_BYTES>>>(x, out);
    vq_final<<<1, 1>>>(out);
}